// round 1
// baseline (speedup 1.0000x reference)
#include <cuda_runtime.h>

// Problem dims (fixed by the reference)
#define BSZ 4
#define TLEN 2048
#define CDIM 1024
#define NH 16
#define HD 64
#define MROWS (BSZ * TLEN)   // 8192

// Scratch (device globals: allocation-free per harness rules)
__device__ float g_q[BSZ * NH * TLEN * HD];    // [b,h,t,d]
__device__ float g_k[BSZ * NH * TLEN * HD];
__device__ float g_v[BSZ * NH * TLEN * HD];
__device__ float g_att[MROWS * CDIM];          // [b*t, h*d]  (row-major like x)

// ---------------------------------------------------------------------------
// GEMM: out[m,n] = sum_k A[m,k] * W[n,k] + bias[n]
// M=8192, N=1024, K=1024. 128x128 block tile, 16 k-slice, 8x8 per thread,
// 256 threads, single-stage register prefetch to hide LDG latency.
// ---------------------------------------------------------------------------
__device__ __forceinline__ void gemm_body(const float* __restrict__ A,
                                          const float* __restrict__ W,
                                          const float* __restrict__ bias,
                                          float* __restrict__ dst,
                                          bool head_layout)
{
    __shared__ float As[16][132];   // [k][m], pad 132 for bank spread + 16B align
    __shared__ float Bs[16][132];   // [k][n]

    const int tid = threadIdx.x;
    const int tx = tid & 15;        // n-block 0..15
    const int ty = tid >> 4;        // m-block 0..15
    const int m0 = blockIdx.y * 128;
    const int n0 = blockIdx.x * 128;

    float acc[8][8];
#pragma unroll
    for (int r = 0; r < 8; r++)
#pragma unroll
        for (int c = 0; c < 8; c++) acc[r][c] = 0.f;

    // Each thread loads 2 float4 from A and 2 from W per k-slice.
    const int row0 = tid >> 2;      // 0..63
    const int c4   = tid & 3;       // 0..3  (k-subchunk)
    const float* aptr0 = A + (size_t)(m0 + row0)      * 1024 + c4 * 4;
    const float* aptr1 = A + (size_t)(m0 + row0 + 64) * 1024 + c4 * 4;
    const float* wptr0 = W + (size_t)(n0 + row0)      * 1024 + c4 * 4;
    const float* wptr1 = W + (size_t)(n0 + row0 + 64) * 1024 + c4 * 4;

    float4 pa0 = *(const float4*)(aptr0);
    float4 pa1 = *(const float4*)(aptr1);
    float4 pb0 = *(const float4*)(wptr0);
    float4 pb1 = *(const float4*)(wptr1);

    for (int kt = 0; kt < 64; kt++) {
        // commit staged tile to smem (transposed to [k][m]/[k][n])
        As[c4 * 4 + 0][row0] = pa0.x; As[c4 * 4 + 1][row0] = pa0.y;
        As[c4 * 4 + 2][row0] = pa0.z; As[c4 * 4 + 3][row0] = pa0.w;
        As[c4 * 4 + 0][row0 + 64] = pa1.x; As[c4 * 4 + 1][row0 + 64] = pa1.y;
        As[c4 * 4 + 2][row0 + 64] = pa1.z; As[c4 * 4 + 3][row0 + 64] = pa1.w;
        Bs[c4 * 4 + 0][row0] = pb0.x; Bs[c4 * 4 + 1][row0] = pb0.y;
        Bs[c4 * 4 + 2][row0] = pb0.z; Bs[c4 * 4 + 3][row0] = pb0.w;
        Bs[c4 * 4 + 0][row0 + 64] = pb1.x; Bs[c4 * 4 + 1][row0 + 64] = pb1.y;
        Bs[c4 * 4 + 2][row0 + 64] = pb1.z; Bs[c4 * 4 + 3][row0 + 64] = pb1.w;
        __syncthreads();

        // prefetch next slice (LDG latency overlaps the FMA loop below)
        if (kt + 1 < 64) {
            const int off = (kt + 1) * 16;
            pa0 = *(const float4*)(aptr0 + off);
            pa1 = *(const float4*)(aptr1 + off);
            pb0 = *(const float4*)(wptr0 + off);
            pb1 = *(const float4*)(wptr1 + off);
        }

#pragma unroll
        for (int kk = 0; kk < 16; kk++) {
            float a[8], b[8];
            *(float4*)&a[0] = *(const float4*)&As[kk][ty * 8];
            *(float4*)&a[4] = *(const float4*)&As[kk][ty * 8 + 4];
            *(float4*)&b[0] = *(const float4*)&Bs[kk][tx * 8];
            *(float4*)&b[4] = *(const float4*)&Bs[kk][tx * 8 + 4];
#pragma unroll
            for (int r = 0; r < 8; r++)
#pragma unroll
                for (int c = 0; c < 8; c++)
                    acc[r][c] = fmaf(a[r], b[c], acc[r][c]);
        }
        __syncthreads();
    }

    // epilogue
    float bfrag[8];
#pragma unroll
    for (int j = 0; j < 8; j++) bfrag[j] = bias[n0 + tx * 8 + j];

    if (head_layout) {
        // dst is [b, h, t, d]; an 8-wide n-block never crosses a 64-wide head.
        const int n = n0 + tx * 8;
        const int h = n >> 6;
        const int d = n & 63;
#pragma unroll
        for (int r = 0; r < 8; r++) {
            const int m = m0 + ty * 8 + r;
            const int bb = m >> 11;          // / 2048
            const int t  = m & 2047;
            float* p = dst + (((size_t)(bb * NH + h) * TLEN + t) * HD + d);
            float4 o0, o1;
            o0.x = acc[r][0] + bfrag[0]; o0.y = acc[r][1] + bfrag[1];
            o0.z = acc[r][2] + bfrag[2]; o0.w = acc[r][3] + bfrag[3];
            o1.x = acc[r][4] + bfrag[4]; o1.y = acc[r][5] + bfrag[5];
            o1.z = acc[r][6] + bfrag[6]; o1.w = acc[r][7] + bfrag[7];
            *(float4*)(p)     = o0;
            *(float4*)(p + 4) = o1;
        }
    } else {
#pragma unroll
        for (int r = 0; r < 8; r++) {
            const int m = m0 + ty * 8 + r;
            float* p = dst + (size_t)m * CDIM + n0 + tx * 8;
            float4 o0, o1;
            o0.x = acc[r][0] + bfrag[0]; o0.y = acc[r][1] + bfrag[1];
            o0.z = acc[r][2] + bfrag[2]; o0.w = acc[r][3] + bfrag[3];
            o1.x = acc[r][4] + bfrag[4]; o1.y = acc[r][5] + bfrag[5];
            o1.z = acc[r][6] + bfrag[6]; o1.w = acc[r][7] + bfrag[7];
            *(float4*)(p)     = o0;
            *(float4*)(p + 4) = o1;
        }
    }
}

__global__ __launch_bounds__(256, 2)
void gemm_qkv_kernel(const float* __restrict__ x,
                     const float* __restrict__ Wq, const float* __restrict__ bq,
                     const float* __restrict__ Wk, const float* __restrict__ bk,
                     const float* __restrict__ Wv, const float* __restrict__ bv)
{
    const float* W; const float* bias; float* dst;
    if (blockIdx.z == 0)      { W = Wq; bias = bq; dst = g_q; }
    else if (blockIdx.z == 1) { W = Wk; bias = bk; dst = g_k; }
    else                      { W = Wv; bias = bv; dst = g_v; }
    gemm_body(x, W, bias, dst, true);
}

__global__ __launch_bounds__(256, 2)
void gemm_proj_kernel(const float* __restrict__ Wp, const float* __restrict__ bp,
                      float* __restrict__ out)
{
    gemm_body(g_att, Wp, bp, out, false);
}

// ---------------------------------------------------------------------------
// Flash attention (causal), fp32. One block = (b,h) x 64-query tile.
// 256 threads; 4x4 micro-tile per thread for both S=QK^T and O+=P*V.
// K stored transposed in smem ([d][j]) so the b-fragment is an aligned LDS.128.
// Rows padded to 68 floats (272B: 16B-aligned, bank-spread).
// ---------------------------------------------------------------------------
#define FROW 68
#define FLASH_SMEM ((4 * 64 * FROW + 3 * 64) * (int)sizeof(float))

extern __shared__ float sm_flash[];

__global__ __launch_bounds__(256)
void flash_kernel()
{
    float* Qs   = sm_flash;                 // [64][68]  (q rows, d cols)
    float* Kst  = Qs  + 64 * FROW;          // [64][68]  (d rows, j cols)  transposed
    float* Vs   = Kst + 64 * FROW;          // [64][68]  (j rows, d cols)
    float* Ss   = Vs  + 64 * FROW;          // [64][68]  (q rows, j cols)
    float* mrow = Ss  + 64 * FROW;          // [64]
    float* lrow = mrow + 64;                // [64]
    float* arow = lrow + 64;                // [64]

    const int tid = threadIdx.x;
    const int tx = tid & 15;                // j/d block
    const int ty = tid >> 4;                // q block
    const int bh = blockIdx.y;              // b*NH + h
    const int qb = blockIdx.x;
    const int q0 = qb * 64;

    const float* qptr = g_q + ((size_t)bh * TLEN + q0) * HD;

    // Load Q tile (row-major [i][d], float4)
#pragma unroll
    for (int i = 0; i < 4; i++) {
        const int fidx = tid + i * 256;     // 0..1023
        const int row = fidx >> 4;
        const int c4 = fidx & 15;
        *(float4*)&Qs[row * FROW + c4 * 4] =
            *(const float4*)(qptr + row * HD + c4 * 4);
    }
    if (tid < 64) { mrow[tid] = -1e30f; lrow[tid] = 0.f; }

    float acc[4][4];
#pragma unroll
    for (int r = 0; r < 4; r++)
#pragma unroll
        for (int c = 0; c < 4; c++) acc[r][c] = 0.f;

    for (int kt = 0; kt <= qb; kt++) {
        const int k0 = kt * 64;
        const float* kptr = g_k + ((size_t)bh * TLEN + k0) * HD;
        const float* vptr = g_v + ((size_t)bh * TLEN + k0) * HD;

        __syncthreads();   // Q ready (iter 0) / previous tile fully consumed

        // Load K (transposed into [d][j]) and V ([j][d])
#pragma unroll
        for (int i = 0; i < 4; i++) {
            const int fidx = tid + i * 256;
            const int j = fidx >> 4;
            const int c4 = fidx & 15;
            float4 kv = *(const float4*)(kptr + j * HD + c4 * 4);
            Kst[(c4 * 4 + 0) * FROW + j] = kv.x;
            Kst[(c4 * 4 + 1) * FROW + j] = kv.y;
            Kst[(c4 * 4 + 2) * FROW + j] = kv.z;
            Kst[(c4 * 4 + 3) * FROW + j] = kv.w;
            *(float4*)&Vs[j * FROW + c4 * 4] =
                *(const float4*)(vptr + j * HD + c4 * 4);
        }
        __syncthreads();

        // S = Q K^T (4x4 per thread)
        float s[4][4];
#pragma unroll
        for (int r = 0; r < 4; r++)
#pragma unroll
            for (int c = 0; c < 4; c++) s[r][c] = 0.f;

#pragma unroll 4
        for (int d = 0; d < 64; d++) {
            float a0 = Qs[(ty * 4 + 0) * FROW + d];
            float a1 = Qs[(ty * 4 + 1) * FROW + d];
            float a2 = Qs[(ty * 4 + 2) * FROW + d];
            float a3 = Qs[(ty * 4 + 3) * FROW + d];
            float4 bv4 = *(const float4*)&Kst[d * FROW + tx * 4];
            s[0][0] = fmaf(a0, bv4.x, s[0][0]); s[0][1] = fmaf(a0, bv4.y, s[0][1]);
            s[0][2] = fmaf(a0, bv4.z, s[0][2]); s[0][3] = fmaf(a0, bv4.w, s[0][3]);
            s[1][0] = fmaf(a1, bv4.x, s[1][0]); s[1][1] = fmaf(a1, bv4.y, s[1][1]);
            s[1][2] = fmaf(a1, bv4.z, s[1][2]); s[1][3] = fmaf(a1, bv4.w, s[1][3]);
            s[2][0] = fmaf(a2, bv4.x, s[2][0]); s[2][1] = fmaf(a2, bv4.y, s[2][1]);
            s[2][2] = fmaf(a2, bv4.z, s[2][2]); s[2][3] = fmaf(a2, bv4.w, s[2][3]);
            s[3][0] = fmaf(a3, bv4.x, s[3][0]); s[3][1] = fmaf(a3, bv4.y, s[3][1]);
            s[3][2] = fmaf(a3, bv4.z, s[3][2]); s[3][3] = fmaf(a3, bv4.w, s[3][3]);
        }

        // scale + causal mask + store to Ss
        const float scale = 0.125f;  // 1/sqrt(64)
        const bool diag = (kt == qb);
#pragma unroll
        for (int r = 0; r < 4; r++) {
            const int qi = q0 + ty * 4 + r;
            float4 o;
            float v0 = s[r][0] * scale, v1 = s[r][1] * scale;
            float v2 = s[r][2] * scale, v3 = s[r][3] * scale;
            if (diag) {
                const int kjb = k0 + tx * 4;
                if (kjb + 0 > qi) v0 = -1e30f;
                if (kjb + 1 > qi) v1 = -1e30f;
                if (kjb + 2 > qi) v2 = -1e30f;
                if (kjb + 3 > qi) v3 = -1e30f;
            }
            o.x = v0; o.y = v1; o.z = v2; o.w = v3;
            *(float4*)&Ss[(ty * 4 + r) * FROW + tx * 4] = o;
        }
        __syncthreads();

        // online softmax: one thread per query row
        if (tid < 64) {
            const int r = tid;
            float mprev = mrow[r];
            float mnew = mprev;
#pragma unroll 8
            for (int j = 0; j < 64; j++)
                mnew = fmaxf(mnew, Ss[r * FROW + j]);
            const float alpha = __expf(mprev - mnew);
            float lsum = 0.f;
#pragma unroll 8
            for (int j = 0; j < 64; j++) {
                float p = __expf(Ss[r * FROW + j] - mnew);
                Ss[r * FROW + j] = p;
                lsum += p;
            }
            lrow[r] = lrow[r] * alpha + lsum;
            mrow[r] = mnew;
            arow[r] = alpha;
        }
        __syncthreads();

        // rescale accumulators and accumulate O += P * V
        float al[4];
#pragma unroll
        for (int r = 0; r < 4; r++) al[r] = arow[ty * 4 + r];
#pragma unroll
        for (int r = 0; r < 4; r++)
#pragma unroll
            for (int c = 0; c < 4; c++) acc[r][c] *= al[r];

#pragma unroll 4
        for (int kk = 0; kk < 64; kk++) {
            float a0 = Ss[(ty * 4 + 0) * FROW + kk];
            float a1 = Ss[(ty * 4 + 1) * FROW + kk];
            float a2 = Ss[(ty * 4 + 2) * FROW + kk];
            float a3 = Ss[(ty * 4 + 3) * FROW + kk];
            float4 bv4 = *(const float4*)&Vs[kk * FROW + tx * 4];
            acc[0][0] = fmaf(a0, bv4.x, acc[0][0]); acc[0][1] = fmaf(a0, bv4.y, acc[0][1]);
            acc[0][2] = fmaf(a0, bv4.z, acc[0][2]); acc[0][3] = fmaf(a0, bv4.w, acc[0][3]);
            acc[1][0] = fmaf(a1, bv4.x, acc[1][0]); acc[1][1] = fmaf(a1, bv4.y, acc[1][1]);
            acc[1][2] = fmaf(a1, bv4.z, acc[1][2]); acc[1][3] = fmaf(a1, bv4.w, acc[1][3]);
            acc[2][0] = fmaf(a2, bv4.x, acc[2][0]); acc[2][1] = fmaf(a2, bv4.y, acc[2][1]);
            acc[2][2] = fmaf(a2, bv4.z, acc[2][2]); acc[2][3] = fmaf(a2, bv4.w, acc[2][3]);
            acc[3][0] = fmaf(a3, bv4.x, acc[3][0]); acc[3][1] = fmaf(a3, bv4.y, acc[3][1]);
            acc[3][2] = fmaf(a3, bv4.z, acc[3][2]); acc[3][3] = fmaf(a3, bv4.w, acc[3][3]);
        }
    }

    // write O tile to g_att in [b*t, h*64+d] layout
    const int b = bh / NH;
    const int h = bh % NH;
#pragma unroll
    for (int r = 0; r < 4; r++) {
        const int row = q0 + ty * 4 + r;
        const float inv = 1.f / lrow[ty * 4 + r];
        float4 o;
        o.x = acc[r][0] * inv; o.y = acc[r][1] * inv;
        o.z = acc[r][2] * inv; o.w = acc[r][3] * inv;
        *(float4*)(g_att + ((size_t)b * TLEN + row) * CDIM + h * HD + tx * 4) = o;
    }
}

// ---------------------------------------------------------------------------
extern "C" void kernel_launch(void* const* d_in, const int* in_sizes, int n_in,
                              void* d_out, int out_size)
{
    (void)in_sizes; (void)n_in; (void)out_size;
    const float* x  = (const float*)d_in[0];
    const float* Wq = (const float*)d_in[1];
    const float* bq = (const float*)d_in[2];
    const float* Wk = (const float*)d_in[3];
    const float* bk = (const float*)d_in[4];
    const float* Wv = (const float*)d_in[5];
    const float* bv = (const float*)d_in[6];
    const float* Wp = (const float*)d_in[7];
    const float* bp = (const float*)d_in[8];
    float* out = (float*)d_out;

    // QKV projections: grid (N/128, M/128, 3)
    gemm_qkv_kernel<<<dim3(CDIM / 128, MROWS / 128, 3), 256>>>(
        x, Wq, bq, Wk, bk, Wv, bv);

    // Flash attention: grid (T/64, B*H)
    cudaFuncSetAttribute(flash_kernel,
                         cudaFuncAttributeMaxDynamicSharedMemorySize, FLASH_SMEM);
    flash_kernel<<<dim3(TLEN / 64, BSZ * NH), 256, FLASH_SMEM>>>();

    // Output projection
    gemm_proj_kernel<<<dim3(CDIM / 128, MROWS / 128), 256>>>(Wp, bp, out);
}

// round 3
// speedup vs baseline: 3.4179x; 3.4179x over previous
#include <cuda_runtime.h>
#include <cuda_fp16.h>
#include <cuda_bf16.h>
#include <cstdint>

#define BSZ 4
#define TLEN 2048
#define CDIM 1024
#define NH 16
#define HD 64
#define MROWS 8192
#define KCAT 3072
#define NCHUNK 48          // KCAT / 64

// ---------------- scratch ----------------
__device__ __half g_q[(size_t)MROWS * HD * NH / 16 * 16];     // 8.39M halves [b,h,t,d]
__device__ __half g_k[(size_t)MROWS * HD * NH / 16 * 16];
__device__ __half g_v[(size_t)MROWS * HD * NH / 16 * 16];
__device__ __nv_bfloat16 g_xcat[(size_t)MROWS * KCAT];        // acts  [hi|lo|hi]
__device__ __nv_bfloat16 g_acat[(size_t)MROWS * KCAT];        // attn out, same layout
__device__ __nv_bfloat16 g_wcat[(size_t)4 * CDIM * KCAT];     // weights [hi|hi|lo] x4

// ---------------- PTX helpers ----------------
__device__ __forceinline__ uint32_t cvta_sm(const void* p) {
    uint32_t a;
    asm("{ .reg .u64 t; cvta.to.shared.u64 t, %1; cvt.u32.u64 %0, t; }" : "=r"(a) : "l"(p));
    return a;
}
__device__ __forceinline__ void cp16(uint32_t s, const void* g) {
    asm volatile("cp.async.cg.shared.global [%0], [%1], 16;" :: "r"(s), "l"(g));
}
__device__ __forceinline__ void cp16ca(uint32_t s, const void* g) {
    asm volatile("cp.async.ca.shared.global [%0], [%1], 16;" :: "r"(s), "l"(g));
}
#define CP_COMMIT() asm volatile("cp.async.commit_group;" ::: "memory")
#define CP_WAIT0()  asm volatile("cp.async.wait_group 0;" ::: "memory")
#define CP_WAIT1()  asm volatile("cp.async.wait_group 1;" ::: "memory")
#define CP_WAIT2()  asm volatile("cp.async.wait_group 2;" ::: "memory")

__device__ __forceinline__ void ldsm4(uint32_t* r, uint32_t a) {
    asm volatile("ldmatrix.sync.aligned.m8n8.x4.shared.b16 {%0,%1,%2,%3}, [%4];"
                 : "=r"(r[0]), "=r"(r[1]), "=r"(r[2]), "=r"(r[3]) : "r"(a));
}
__device__ __forceinline__ void ldsm4t(uint32_t* r, uint32_t a) {
    asm volatile("ldmatrix.sync.aligned.m8n8.x4.trans.shared.b16 {%0,%1,%2,%3}, [%4];"
                 : "=r"(r[0]), "=r"(r[1]), "=r"(r[2]), "=r"(r[3]) : "r"(a));
}
__device__ __forceinline__ void mma_bf16(float* c, const uint32_t* a, const uint32_t* b) {
    asm volatile(
        "mma.sync.aligned.m16n8k16.row.col.f32.bf16.bf16.f32 "
        "{%0,%1,%2,%3}, {%4,%5,%6,%7}, {%8,%9}, {%0,%1,%2,%3};"
        : "+f"(c[0]), "+f"(c[1]), "+f"(c[2]), "+f"(c[3])
        : "r"(a[0]), "r"(a[1]), "r"(a[2]), "r"(a[3]), "r"(b[0]), "r"(b[1]));
}
__device__ __forceinline__ void mma_f16(float* c, const uint32_t* a, const uint32_t* b) {
    asm volatile(
        "mma.sync.aligned.m16n8k16.row.col.f32.f16.f16.f32 "
        "{%0,%1,%2,%3}, {%4,%5,%6,%7}, {%8,%9}, {%0,%1,%2,%3};"
        : "+f"(c[0]), "+f"(c[1]), "+f"(c[2]), "+f"(c[3])
        : "r"(a[0]), "r"(a[1]), "r"(a[2]), "r"(a[3]), "r"(b[0]), "r"(b[1]));
}
__device__ __forceinline__ uint32_t packh2(float lo, float hi) {  // f16x2 {lo, hi}
    uint32_t d;
    asm("cvt.rn.f16x2.f32 %0, %1, %2;" : "=r"(d) : "f"(hi), "f"(lo));
    return d;
}
__device__ __forceinline__ uint32_t packbf2(float lo, float hi) { // bf16x2 {lo, hi}
    uint32_t d;
    asm("cvt.rn.bf16x2.f32 %0, %1, %2;" : "=r"(d) : "f"(hi), "f"(lo));
    return d;
}
__device__ __forceinline__ uint32_t hmul2(uint32_t a, uint32_t b) {
    uint32_t d;
    asm("mul.f16x2 %0, %1, %2;" : "=r"(d) : "r"(a), "r"(b));
    return d;
}

// ---------------------------------------------------------------------------
// Split fp32 -> concatenated bf16 hi/lo
// ---------------------------------------------------------------------------
__global__ void split_act(const float* __restrict__ in)
{
    const int r = blockIdx.x, q = threadIdx.x * 4;
    float4 v = *(const float4*)(in + (size_t)r * CDIM + q);
    float f[4] = {v.x, v.y, v.z, v.w}, lo[4];
#pragma unroll
    for (int j = 0; j < 4; j++)
        lo[j] = f[j] - __bfloat162float(__float2bfloat16_rn(f[j]));
    uint2 hp = {packbf2(f[0], f[1]), packbf2(f[2], f[3])};
    uint2 lp = {packbf2(lo[0], lo[1]), packbf2(lo[2], lo[3])};
    __nv_bfloat16* o = g_xcat + (size_t)r * KCAT + q;
    *(uint2*)(o) = hp; *(uint2*)(o + CDIM) = lp; *(uint2*)(o + 2 * CDIM) = hp;
}
__global__ void split_wt(const float* __restrict__ W, int z)
{
    const int r = blockIdx.x, q = threadIdx.x * 4;
    float4 v = *(const float4*)(W + (size_t)r * CDIM + q);
    float f[4] = {v.x, v.y, v.z, v.w}, lo[4];
#pragma unroll
    for (int j = 0; j < 4; j++)
        lo[j] = f[j] - __bfloat162float(__float2bfloat16_rn(f[j]));
    uint2 hp = {packbf2(f[0], f[1]), packbf2(f[2], f[3])};
    uint2 lp = {packbf2(lo[0], lo[1]), packbf2(lo[2], lo[3])};
    __nv_bfloat16* o = g_wcat + (size_t)z * CDIM * KCAT + (size_t)r * KCAT + q;
    *(uint2*)(o) = hp; *(uint2*)(o + CDIM) = hp; *(uint2*)(o + 2 * CDIM) = lp;
}

// ---------------------------------------------------------------------------
// HMMA GEMM: D[m,n] = A_cat[m,:] . W_cat[n,:] + bias[n]
// CTA 128x128, 8 warps (2m x 4n), warp 64x32. k-chunk 64, 2-stage cp.async.
// smem rows padded to 72 halves (144B) -> conflict-free ldmatrix.
// ---------------------------------------------------------------------------
#define ROWB 144
#define ATILE (128 * ROWB)      // 18432
#define STG2  (2 * ATILE)       // 36864
#define GSM   (2 * STG2)        // 73728

__device__ __forceinline__ void gemm_mma(const __nv_bfloat16* __restrict__ A,
                                         const __nv_bfloat16* __restrict__ W,
                                         const float* __restrict__ bias,
                                         __half* dsth, float* dstf, int head)
{
    extern __shared__ char sm_g[];
    const uint32_t sb = cvta_sm(sm_g);
    const int tid = threadIdx.x, lane = tid & 31, wid = tid >> 5;
    const int m0 = blockIdx.y * 128, n0 = blockIdx.x * 128;
    const int wm = wid & 1, wn = wid >> 1;
    const int gid = lane >> 2, tig = lane & 3;

    const int lr = tid >> 3, lc = tid & 7;
    const __nv_bfloat16* gA = A + (size_t)(m0 + lr) * KCAT + lc * 8;
    const __nv_bfloat16* gW = W + (size_t)(n0 + lr) * KCAT + lc * 8;
    const uint32_t sA0 = sb + lr * ROWB + lc * 16;
    const uint32_t sW0 = sA0 + ATILE;

#define GLOAD(ch, st) do {                                                      \
        const uint32_t _o = (uint32_t)(st) * STG2;                              \
        _Pragma("unroll")                                                       \
        for (int _i = 0; _i < 4; _i++) {                                        \
            cp16ca(sA0 + _o + _i * 32 * ROWB, gA + (size_t)_i * 32 * KCAT + (ch) * 64); \
            cp16  (sW0 + _o + _i * 32 * ROWB, gW + (size_t)_i * 32 * KCAT + (ch) * 64); \
        }                                                                       \
        CP_COMMIT();                                                            \
    } while (0)

    float acc[4][4][4];
#pragma unroll
    for (int i = 0; i < 4; i++)
#pragma unroll
        for (int j = 0; j < 4; j++)
#pragma unroll
            for (int t = 0; t < 4; t++) acc[i][j][t] = 0.f;

    const uint32_t aB = sb + (wm * 64 + (lane & 15)) * ROWB + (lane >> 4) * 16;
    const uint32_t bB = sb + ATILE + (wn * 32 + (lane >> 4) * 8 + (lane & 7)) * ROWB
                      + ((lane >> 3) & 1) * 16;

    GLOAD(0, 0);
    GLOAD(1, 1);

    for (int k = 0; k < NCHUNK; k++) {
        if (k < NCHUNK - 1) { CP_WAIT1(); } else { CP_WAIT0(); }
        __syncthreads();
        const uint32_t so = (uint32_t)(k & 1) * STG2;
#pragma unroll
        for (int ck = 0; ck < 4; ck++) {
            uint32_t a[4][4], b[4][2];
#pragma unroll
            for (int mt = 0; mt < 4; mt++)
                ldsm4(a[mt], aB + so + mt * 16 * ROWB + ck * 32);
#pragma unroll
            for (int np = 0; np < 2; np++) {
                uint32_t r[4];
                ldsm4(r, bB + so + np * 16 * ROWB + ck * 32);
                b[2 * np][0] = r[0]; b[2 * np][1] = r[1];
                b[2 * np + 1][0] = r[2]; b[2 * np + 1][1] = r[3];
            }
#pragma unroll
            for (int mt = 0; mt < 4; mt++)
#pragma unroll
                for (int nt = 0; nt < 4; nt++)
                    mma_bf16(acc[mt][nt], a[mt], b[nt]);
        }
        __syncthreads();
        if (k + 2 < NCHUNK) GLOAD(k + 2, k & 1);
    }
#undef GLOAD

    // epilogue
#pragma unroll
    for (int mt = 0; mt < 4; mt++) {
        const int mr0 = m0 + wm * 64 + mt * 16 + gid;
#pragma unroll
        for (int nt = 0; nt < 4; nt++) {
            const int n = n0 + wn * 32 + nt * 8 + tig * 2;
            const float b0 = bias[n], b1 = bias[n + 1];
            const float v00 = acc[mt][nt][0] + b0, v01 = acc[mt][nt][1] + b1;
            const float v10 = acc[mt][nt][2] + b0, v11 = acc[mt][nt][3] + b1;
            if (head) {
                const int h = n >> 6, d = n & 63;
                {
                    const int m = mr0, bb = m >> 11, t = m & 2047;
                    *(uint32_t*)(dsth + (((size_t)(bb * NH + h)) * TLEN + t) * HD + d)
                        = packh2(v00, v01);
                }
                {
                    const int m = mr0 + 8, bb = m >> 11, t = m & 2047;
                    *(uint32_t*)(dsth + (((size_t)(bb * NH + h)) * TLEN + t) * HD + d)
                        = packh2(v10, v11);
                }
            } else {
                float2 p0 = {v00, v01}, p1 = {v10, v11};
                *(float2*)(dstf + (size_t)mr0 * CDIM + n) = p0;
                *(float2*)(dstf + (size_t)(mr0 + 8) * CDIM + n) = p1;
            }
        }
    }
}

__global__ __launch_bounds__(256, 2)
void mm_qkv(const float* __restrict__ bq, const float* __restrict__ bk,
            const float* __restrict__ bv)
{
    const int z = blockIdx.z;
    const __nv_bfloat16* W = g_wcat + (size_t)z * CDIM * KCAT;
    const float* bias = (z == 0) ? bq : (z == 1) ? bk : bv;
    __half* dst = (z == 0) ? g_q : (z == 1) ? g_k : g_v;
    gemm_mma(g_xcat, W, bias, dst, nullptr, 1);
}
__global__ __launch_bounds__(256, 2)
void mm_proj(const float* __restrict__ bp, float* __restrict__ out)
{
    gemm_mma(g_acat, g_wcat + (size_t)3 * CDIM * KCAT, bp, nullptr, out, 0);
}

// ---------------------------------------------------------------------------
// Flash attention, HMMA fp16. CTA = 128 q rows x one (b,h); 8 warps x 16 rows.
// K/V chunks of 64, double-buffered cp.async. Register online softmax.
// Epilogue writes split-bf16 directly into g_acat.
// ---------------------------------------------------------------------------
#define QOFF 0
#define KOFF 18432
#define KVST 18432
#define FSM  55296

__global__ __launch_bounds__(256, 2)
void flash_mma()
{
    extern __shared__ char sm_f[];
    const uint32_t sb = cvta_sm(sm_f);
    const int tid = threadIdx.x, lane = tid & 31, wid = tid >> 5;
    const int gid = lane >> 2, tig = lane & 3;
    const int bh = blockIdx.y;
    const int qb = 15 - blockIdx.x;          // big tiles first (LPT)
    const int q0 = qb * 128;
    const int nc = 2 * (qb + 1);

    const __half* qg = g_q + (size_t)bh * TLEN * HD;
    const __half* kg = g_k + (size_t)bh * TLEN * HD;
    const __half* vg = g_v + (size_t)bh * TLEN * HD;

    // Q load (group 0)
#pragma unroll
    for (int i = 0; i < 4; i++) {
        const int r = (tid >> 3) + 32 * i;
        cp16(sb + QOFF + r * ROWB + (tid & 7) * 16,
             qg + ((size_t)(q0 + r)) * HD + (tid & 7) * 8);
    }
    CP_COMMIT();

#define KVLOAD(c, st) do {                                                      \
        const uint32_t _ko = KOFF + (uint32_t)(st) * KVST;                      \
        _Pragma("unroll")                                                       \
        for (int _i = 0; _i < 2; _i++) {                                        \
            const int _r = (tid >> 3) + 32 * _i;                                \
            cp16(_ko + sb - sb + sb + _ko * 0 + sb + 0, nullptr);               \
        }                                                                       \
    } while (0)
#undef KVLOAD
#define KVLOAD(c, st) do {                                                      \
        const uint32_t _ko = sb + KOFF + (uint32_t)(st) * KVST;                 \
        _Pragma("unroll")                                                       \
        for (int _i = 0; _i < 2; _i++) {                                        \
            const int _r = (tid >> 3) + 32 * _i;                                \
            cp16(_ko + _r * ROWB + (tid & 7) * 16,                              \
                 kg + ((size_t)(c) * 64 + _r) * HD + (tid & 7) * 8);            \
            cp16(_ko + 9216 + _r * ROWB + (tid & 7) * 16,                       \
                 vg + ((size_t)(c) * 64 + _r) * HD + (tid & 7) * 8);            \
        }                                                                       \
        CP_COMMIT();                                                            \
    } while (0)

    KVLOAD(0, 0);
    KVLOAD(1, 1);

    // Q fragments (scaled by 1/8)
    CP_WAIT2();
    __syncthreads();
    uint32_t qf[4][4];
    {
        const uint32_t qaB = sb + QOFF + (wid * 16 + (lane & 15)) * ROWB + (lane >> 4) * 16;
#pragma unroll
        for (int ck = 0; ck < 4; ck++) {
            ldsm4(qf[ck], qaB + ck * 32);
#pragma unroll
            for (int i = 0; i < 4; i++) qf[ck][i] = hmul2(qf[ck][i], 0x30003000u); // x0.125
        }
    }

    float o[8][4];
#pragma unroll
    for (int nt = 0; nt < 8; nt++)
#pragma unroll
        for (int t = 0; t < 4; t++) o[nt][t] = 0.f;
    float m0r = -1e30f, m1r = -1e30f, l0 = 0.f, l1 = 0.f;

    for (int c = 0; c < nc; c++) {
        if (c < nc - 1) { CP_WAIT1(); } else { CP_WAIT0(); }
        __syncthreads();
        const uint32_t kof = sb + KOFF + (uint32_t)(c & 1) * KVST;
        const int k0 = c * 64;
        const bool active = (k0 <= q0 + wid * 16 + 15);

        if (active) {
            // S = Q K^T
            float s[8][4];
#pragma unroll
            for (int jt = 0; jt < 8; jt++)
#pragma unroll
                for (int t = 0; t < 4; t++) s[jt][t] = 0.f;

            const uint32_t kbB = kof + ((lane >> 4) * 8 + (lane & 7)) * ROWB
                               + ((lane >> 3) & 1) * 16;
#pragma unroll
            for (int ck = 0; ck < 4; ck++) {
                uint32_t b[8][2];
#pragma unroll
                for (int jp = 0; jp < 4; jp++) {
                    uint32_t r[4];
                    ldsm4(r, kbB + jp * 16 * ROWB + ck * 32);
                    b[2 * jp][0] = r[0]; b[2 * jp][1] = r[1];
                    b[2 * jp + 1][0] = r[2]; b[2 * jp + 1][1] = r[3];
                }
#pragma unroll
                for (int jt = 0; jt < 8; jt++) mma_f16(s[jt], qf[ck], b[jt]);
            }

            // causal mask (boundary chunks only)
            if (k0 + 63 > q0 + wid * 16) {
                const int r0w = q0 + wid * 16 + gid;
#pragma unroll
                for (int jt = 0; jt < 8; jt++) {
                    const int cl = k0 + jt * 8 + tig * 2;
                    if (cl > r0w)     s[jt][0] = -1e30f;
                    if (cl + 1 > r0w) s[jt][1] = -1e30f;
                    if (cl > r0w + 8)     s[jt][2] = -1e30f;
                    if (cl + 1 > r0w + 8) s[jt][3] = -1e30f;
                }
            }

            // online softmax
            float mx0 = -1e30f, mx1 = -1e30f;
#pragma unroll
            for (int jt = 0; jt < 8; jt++) {
                mx0 = fmaxf(mx0, fmaxf(s[jt][0], s[jt][1]));
                mx1 = fmaxf(mx1, fmaxf(s[jt][2], s[jt][3]));
            }
            mx0 = fmaxf(mx0, __shfl_xor_sync(0xFFFFFFFF, mx0, 1));
            mx0 = fmaxf(mx0, __shfl_xor_sync(0xFFFFFFFF, mx0, 2));
            mx1 = fmaxf(mx1, __shfl_xor_sync(0xFFFFFFFF, mx1, 1));
            mx1 = fmaxf(mx1, __shfl_xor_sync(0xFFFFFFFF, mx1, 2));
            const float mn0 = fmaxf(m0r, mx0), mn1 = fmaxf(m1r, mx1);
            const float a0 = __expf(m0r - mn0), a1 = __expf(m1r - mn1);
            float s0 = 0.f, s1 = 0.f;
#pragma unroll
            for (int jt = 0; jt < 8; jt++) {
                s[jt][0] = __expf(s[jt][0] - mn0); s0 += s[jt][0];
                s[jt][1] = __expf(s[jt][1] - mn0); s0 += s[jt][1];
                s[jt][2] = __expf(s[jt][2] - mn1); s1 += s[jt][2];
                s[jt][3] = __expf(s[jt][3] - mn1); s1 += s[jt][3];
            }
            s0 += __shfl_xor_sync(0xFFFFFFFF, s0, 1);
            s0 += __shfl_xor_sync(0xFFFFFFFF, s0, 2);
            s1 += __shfl_xor_sync(0xFFFFFFFF, s1, 1);
            s1 += __shfl_xor_sync(0xFFFFFFFF, s1, 2);
            l0 = l0 * a0 + s0; l1 = l1 * a1 + s1;
            m0r = mn0; m1r = mn1;
#pragma unroll
            for (int nt = 0; nt < 8; nt++) {
                o[nt][0] *= a0; o[nt][1] *= a0; o[nt][2] *= a1; o[nt][3] *= a1;
            }

            // P -> fp16 A-fragments (accumulator/A-operand layout identity)
            uint32_t pf[4][4];
#pragma unroll
            for (int ck = 0; ck < 4; ck++) {
                pf[ck][0] = packh2(s[2 * ck][0], s[2 * ck][1]);
                pf[ck][1] = packh2(s[2 * ck][2], s[2 * ck][3]);
                pf[ck][2] = packh2(s[2 * ck + 1][0], s[2 * ck + 1][1]);
                pf[ck][3] = packh2(s[2 * ck + 1][2], s[2 * ck + 1][3]);
            }

            // O += P V
            const uint32_t vbB = kof + 9216 + (((lane >> 3) & 1) * 8 + (lane & 7)) * ROWB
                               + (lane >> 4) * 16;
#pragma unroll
            for (int ck = 0; ck < 4; ck++) {
                uint32_t b[8][2];
#pragma unroll
                for (int np = 0; np < 4; np++) {
                    uint32_t r[4];
                    ldsm4t(r, vbB + ck * 16 * ROWB + np * 32);
                    b[2 * np][0] = r[0]; b[2 * np][1] = r[1];
                    b[2 * np + 1][0] = r[2]; b[2 * np + 1][1] = r[3];
                }
#pragma unroll
                for (int nt = 0; nt < 8; nt++) mma_f16(o[nt], pf[ck], b[nt]);
            }
        }

        __syncthreads();
        if (c + 2 < nc) KVLOAD(c + 2, c & 1);
    }
#undef KVLOAD

    // epilogue: write split-bf16 [hi|lo|hi] rows of g_acat
    const float i0 = 1.f / l0, i1 = 1.f / l1;
    const int b = bh >> 4, h = bh & 15;
    const size_t mr0 = (size_t)b * TLEN + q0 + wid * 16 + gid;
#pragma unroll
    for (int nt = 0; nt < 8; nt++) {
        const int cl = h * 64 + nt * 8 + tig * 2;
        {
            const float v0 = o[nt][0] * i0, v1 = o[nt][1] * i0;
            const float h0 = __bfloat162float(__float2bfloat16_rn(v0));
            const float h1 = __bfloat162float(__float2bfloat16_rn(v1));
            const uint32_t hp = packbf2(v0, v1), lp = packbf2(v0 - h0, v1 - h1);
            __nv_bfloat16* base = g_acat + mr0 * KCAT + cl;
            *(uint32_t*)(base) = hp;
            *(uint32_t*)(base + CDIM) = lp;
            *(uint32_t*)(base + 2 * CDIM) = hp;
        }
        {
            const float v0 = o[nt][2] * i1, v1 = o[nt][3] * i1;
            const float h0 = __bfloat162float(__float2bfloat16_rn(v0));
            const float h1 = __bfloat162float(__float2bfloat16_rn(v1));
            const uint32_t hp = packbf2(v0, v1), lp = packbf2(v0 - h0, v1 - h1);
            __nv_bfloat16* base = g_acat + (mr0 + 8) * KCAT + cl;
            *(uint32_t*)(base) = hp;
            *(uint32_t*)(base + CDIM) = lp;
            *(uint32_t*)(base + 2 * CDIM) = hp;
        }
    }
}

// ---------------------------------------------------------------------------
extern "C" void kernel_launch(void* const* d_in, const int* in_sizes, int n_in,
                              void* d_out, int out_size)
{
    (void)in_sizes; (void)n_in; (void)out_size;
    const float* x  = (const float*)d_in[0];
    const float* Wq = (const float*)d_in[1];
    const float* bq = (const float*)d_in[2];
    const float* Wk = (const float*)d_in[3];
    const float* bk = (const float*)d_in[4];
    const float* Wv = (const float*)d_in[5];
    const float* bv = (const float*)d_in[6];
    const float* Wp = (const float*)d_in[7];
    const float* bp = (const float*)d_in[8];
    float* out = (float*)d_out;

    cudaFuncSetAttribute(mm_qkv, cudaFuncAttributeMaxDynamicSharedMemorySize, GSM);
    cudaFuncSetAttribute(mm_proj, cudaFuncAttributeMaxDynamicSharedMemorySize, GSM);
    cudaFuncSetAttribute(flash_mma, cudaFuncAttributeMaxDynamicSharedMemorySize, FSM);

    split_act<<<MROWS, 256>>>(x);
    split_wt<<<CDIM, 256>>>(Wq, 0);
    split_wt<<<CDIM, 256>>>(Wk, 1);
    split_wt<<<CDIM, 256>>>(Wv, 2);
    split_wt<<<CDIM, 256>>>(Wp, 3);

    mm_qkv<<<dim3(CDIM / 128, MROWS / 128, 3), 256, GSM>>>(bq, bk, bv);
    flash_mma<<<dim3(TLEN / 128, BSZ * NH), 256, FSM>>>();
    mm_proj<<<dim3(CDIM / 128, MROWS / 128), 256, GSM>>>(bp, out);
}

// round 4
// speedup vs baseline: 4.5225x; 1.3232x over previous
#include <cuda_runtime.h>
#include <cuda_fp16.h>
#include <cstdint>

#define BSZ 4
#define TLEN 2048
#define CDIM 1024
#define NH 16
#define HD 64
#define MROWS 8192
#define KCAT 2048
#define NCHUNK 32          // KCAT / 64

// ---------------- scratch ----------------
__device__ __half g_q[(size_t)MROWS * CDIM];     // [b,h,t,d]
__device__ __half g_k[(size_t)MROWS * CDIM];
__device__ __half g_v[(size_t)MROWS * CDIM];
__device__ __half g_xcat[(size_t)MROWS * KCAT];        // acts  [hi|lo]
__device__ __half g_acat[(size_t)MROWS * KCAT];        // attn out [hi|lo]
__device__ __half g_wcat[(size_t)4 * CDIM * KCAT];     // weights [hi|hi] x4

// ---------------- PTX helpers ----------------
__device__ __forceinline__ uint32_t cvta_sm(const void* p) {
    uint32_t a;
    asm("{ .reg .u64 t; cvta.to.shared.u64 t, %1; cvt.u32.u64 %0, t; }" : "=r"(a) : "l"(p));
    return a;
}
__device__ __forceinline__ void cp16(uint32_t s, const void* g) {
    asm volatile("cp.async.cg.shared.global [%0], [%1], 16;" :: "r"(s), "l"(g));
}
__device__ __forceinline__ void cp16ca(uint32_t s, const void* g) {
    asm volatile("cp.async.ca.shared.global [%0], [%1], 16;" :: "r"(s), "l"(g));
}
#define CP_COMMIT() asm volatile("cp.async.commit_group;" ::: "memory")
#define CP_WAIT0()  asm volatile("cp.async.wait_group 0;" ::: "memory")
#define CP_WAIT1()  asm volatile("cp.async.wait_group 1;" ::: "memory")
#define CP_WAIT2()  asm volatile("cp.async.wait_group 2;" ::: "memory")

__device__ __forceinline__ void ldsm4(uint32_t* r, uint32_t a) {
    asm volatile("ldmatrix.sync.aligned.m8n8.x4.shared.b16 {%0,%1,%2,%3}, [%4];"
                 : "=r"(r[0]), "=r"(r[1]), "=r"(r[2]), "=r"(r[3]) : "r"(a));
}
__device__ __forceinline__ void ldsm4t(uint32_t* r, uint32_t a) {
    asm volatile("ldmatrix.sync.aligned.m8n8.x4.trans.shared.b16 {%0,%1,%2,%3}, [%4];"
                 : "=r"(r[0]), "=r"(r[1]), "=r"(r[2]), "=r"(r[3]) : "r"(a));
}
__device__ __forceinline__ void mma_f16(float* c, const uint32_t* a, const uint32_t* b) {
    asm volatile(
        "mma.sync.aligned.m16n8k16.row.col.f32.f16.f16.f32 "
        "{%0,%1,%2,%3}, {%4,%5,%6,%7}, {%8,%9}, {%0,%1,%2,%3};"
        : "+f"(c[0]), "+f"(c[1]), "+f"(c[2]), "+f"(c[3])
        : "r"(a[0]), "r"(a[1]), "r"(a[2]), "r"(a[3]), "r"(b[0]), "r"(b[1]));
}
__device__ __forceinline__ uint32_t packh2(float lo, float hi) {  // f16x2 {lo, hi}
    uint32_t d;
    asm("cvt.rn.f16x2.f32 %0, %1, %2;" : "=r"(d) : "f"(hi), "f"(lo));
    return d;
}
__device__ __forceinline__ uint32_t hmul2(uint32_t a, uint32_t b) {
    uint32_t d;
    asm("mul.f16x2 %0, %1, %2;" : "=r"(d) : "r"(a), "r"(b));
    return d;
}

// ---------------------------------------------------------------------------
// Splits: activations -> [hi|lo] fp16, weights -> [hi|hi] fp16
// ---------------------------------------------------------------------------
__global__ void split_act(const float* __restrict__ in)
{
    const int r = blockIdx.x, q = threadIdx.x * 4;
    float4 v = *(const float4*)(in + (size_t)r * CDIM + q);
    float f[4] = {v.x, v.y, v.z, v.w}, lo[4];
#pragma unroll
    for (int j = 0; j < 4; j++)
        lo[j] = f[j] - __half2float(__float2half_rn(f[j]));
    uint2 hp = {packh2(f[0], f[1]), packh2(f[2], f[3])};
    uint2 lp = {packh2(lo[0], lo[1]), packh2(lo[2], lo[3])};
    __half* o = g_xcat + (size_t)r * KCAT + q;
    *(uint2*)(o) = hp; *(uint2*)(o + CDIM) = lp;
}
__global__ void split_wt(const float* __restrict__ W0, const float* __restrict__ W1,
                         const float* __restrict__ W2, const float* __restrict__ W3)
{
    const int z = blockIdx.y;
    const float* W = (z == 0) ? W0 : (z == 1) ? W1 : (z == 2) ? W2 : W3;
    const int r = blockIdx.x, q = threadIdx.x * 4;
    float4 v = *(const float4*)(W + (size_t)r * CDIM + q);
    uint2 hp = {packh2(v.x, v.y), packh2(v.z, v.w)};
    __half* o = g_wcat + (size_t)z * CDIM * KCAT + (size_t)r * KCAT + q;
    *(uint2*)(o) = hp; *(uint2*)(o + CDIM) = hp;
}

// ---------------------------------------------------------------------------
// HMMA GEMM: D[m,n] = A_cat[m,:] . W_cat[n,:] + bias[n]
// CTA 128x128, 8 warps (2m x 4n), warp 64x32. k-chunk 64, 3-stage cp.async.
// smem rows padded to 72 halves (144B) -> conflict-free ldmatrix.
// ---------------------------------------------------------------------------
#define ROWB 144
#define ATILE (128 * ROWB)      // 18432
#define STG   (2 * ATILE)       // 36864 per stage (A + W)
#define GSM   (3 * STG)         // 110592

__device__ __forceinline__ void gemm_mma(const __half* __restrict__ A,
                                         const __half* __restrict__ W,
                                         const float* __restrict__ bias,
                                         __half* dsth, float* dstf, int head)
{
    extern __shared__ char sm_g[];
    const uint32_t sb = cvta_sm(sm_g);
    const int tid = threadIdx.x, lane = tid & 31, wid = tid >> 5;
    const int m0 = blockIdx.y * 128, n0 = blockIdx.x * 128;
    const int wm = wid & 1, wn = wid >> 1;
    const int gid = lane >> 2, tig = lane & 3;

    const int lr = tid >> 3, lc = tid & 7;
    const __half* gA = A + (size_t)(m0 + lr) * KCAT + lc * 8;
    const __half* gW = W + (size_t)(n0 + lr) * KCAT + lc * 8;
    const uint32_t sA0 = sb + lr * ROWB + lc * 16;
    const uint32_t sW0 = sA0 + ATILE;

#define GLOAD(ch, st) do {                                                      \
        const uint32_t _o = (uint32_t)(st) * STG;                               \
        _Pragma("unroll")                                                       \
        for (int _i = 0; _i < 4; _i++) {                                        \
            cp16ca(sA0 + _o + _i * 32 * ROWB, gA + (size_t)_i * 32 * KCAT + (ch) * 64); \
            cp16  (sW0 + _o + _i * 32 * ROWB, gW + (size_t)_i * 32 * KCAT + (ch) * 64); \
        }                                                                       \
        CP_COMMIT();                                                            \
    } while (0)

    float acc[4][4][4];
#pragma unroll
    for (int i = 0; i < 4; i++)
#pragma unroll
        for (int j = 0; j < 4; j++)
#pragma unroll
            for (int t = 0; t < 4; t++) acc[i][j][t] = 0.f;

    const uint32_t aB = sb + (wm * 64 + (lane & 15)) * ROWB + (lane >> 4) * 16;
    const uint32_t bB = sb + ATILE + (wn * 32 + (lane >> 4) * 8 + (lane & 7)) * ROWB
                      + ((lane >> 3) & 1) * 16;

    GLOAD(0, 0);
    GLOAD(1, 1);
    GLOAD(2, 2);

    for (int k = 0; k < NCHUNK; k++) {
        if (k <= NCHUNK - 3)      { CP_WAIT2(); }
        else if (k == NCHUNK - 2) { CP_WAIT1(); }
        else                      { CP_WAIT0(); }
        __syncthreads();
        const uint32_t so = (uint32_t)(k % 3) * STG;
#pragma unroll
        for (int ck = 0; ck < 4; ck++) {
            uint32_t a[4][4], b[4][2];
#pragma unroll
            for (int mt = 0; mt < 4; mt++)
                ldsm4(a[mt], aB + so + mt * 16 * ROWB + ck * 32);
#pragma unroll
            for (int np = 0; np < 2; np++) {
                uint32_t r[4];
                ldsm4(r, bB + so + np * 16 * ROWB + ck * 32);
                b[2 * np][0] = r[0]; b[2 * np][1] = r[1];
                b[2 * np + 1][0] = r[2]; b[2 * np + 1][1] = r[3];
            }
#pragma unroll
            for (int mt = 0; mt < 4; mt++)
#pragma unroll
                for (int nt = 0; nt < 4; nt++)
                    mma_f16(acc[mt][nt], a[mt], b[nt]);
        }
        __syncthreads();
        if (k + 3 < NCHUNK) GLOAD(k + 3, (k + 3) % 3);
    }
#undef GLOAD

    // epilogue
#pragma unroll
    for (int mt = 0; mt < 4; mt++) {
        const int mr0 = m0 + wm * 64 + mt * 16 + gid;
#pragma unroll
        for (int nt = 0; nt < 4; nt++) {
            const int n = n0 + wn * 32 + nt * 8 + tig * 2;
            const float b0 = bias[n], b1 = bias[n + 1];
            const float v00 = acc[mt][nt][0] + b0, v01 = acc[mt][nt][1] + b1;
            const float v10 = acc[mt][nt][2] + b0, v11 = acc[mt][nt][3] + b1;
            if (head) {
                const int h = n >> 6, d = n & 63;
                {
                    const int m = mr0, bb = m >> 11, t = m & 2047;
                    *(uint32_t*)(dsth + (((size_t)(bb * NH + h)) * TLEN + t) * HD + d)
                        = packh2(v00, v01);
                }
                {
                    const int m = mr0 + 8, bb = m >> 11, t = m & 2047;
                    *(uint32_t*)(dsth + (((size_t)(bb * NH + h)) * TLEN + t) * HD + d)
                        = packh2(v10, v11);
                }
            } else {
                float2 p0 = {v00, v01}, p1 = {v10, v11};
                *(float2*)(dstf + (size_t)mr0 * CDIM + n) = p0;
                *(float2*)(dstf + (size_t)(mr0 + 8) * CDIM + n) = p1;
            }
        }
    }
}

__global__ __launch_bounds__(256, 2)
void mm_qkv(const float* __restrict__ bq, const float* __restrict__ bk,
            const float* __restrict__ bv)
{
    const int z = blockIdx.z;
    const __half* W = g_wcat + (size_t)z * CDIM * KCAT;
    const float* bias = (z == 0) ? bq : (z == 1) ? bk : bv;
    __half* dst = (z == 0) ? g_q : (z == 1) ? g_k : g_v;
    gemm_mma(g_xcat, W, bias, dst, nullptr, 1);
}
__global__ __launch_bounds__(256, 2)
void mm_proj(const float* __restrict__ bp, float* __restrict__ out)
{
    gemm_mma(g_acat, g_wcat + (size_t)3 * CDIM * KCAT, bp, nullptr, out, 0);
}

// ---------------------------------------------------------------------------
// Flash attention, HMMA fp16. CTA = 128 q rows x one (b,h); 8 warps x 16 rows.
// K/V chunks of 64, double-buffered cp.async. Register online softmax.
// Epilogue writes 2-segment fp16 split directly into g_acat.
// ---------------------------------------------------------------------------
#define QOFF 0
#define KOFF 18432
#define KVST 18432
#define FSM  55296

__global__ __launch_bounds__(256, 2)
void flash_mma()
{
    extern __shared__ char sm_f[];
    const uint32_t sb = cvta_sm(sm_f);
    const int tid = threadIdx.x, lane = tid & 31, wid = tid >> 5;
    const int gid = lane >> 2, tig = lane & 3;
    const int bh = blockIdx.y;
    const int qb = 15 - blockIdx.x;          // big tiles first (LPT)
    const int q0 = qb * 128;
    const int nc = 2 * (qb + 1);

    const __half* qg = g_q + (size_t)bh * TLEN * HD;
    const __half* kg = g_k + (size_t)bh * TLEN * HD;
    const __half* vg = g_v + (size_t)bh * TLEN * HD;

    // Q load (group 0)
#pragma unroll
    for (int i = 0; i < 4; i++) {
        const int r = (tid >> 3) + 32 * i;
        cp16(sb + QOFF + r * ROWB + (tid & 7) * 16,
             qg + ((size_t)(q0 + r)) * HD + (tid & 7) * 8);
    }
    CP_COMMIT();

#define KVLOAD(c, st) do {                                                      \
        const uint32_t _ko = sb + KOFF + (uint32_t)(st) * KVST;                 \
        _Pragma("unroll")                                                       \
        for (int _i = 0; _i < 2; _i++) {                                        \
            const int _r = (tid >> 3) + 32 * _i;                                \
            cp16(_ko + _r * ROWB + (tid & 7) * 16,                              \
                 kg + ((size_t)(c) * 64 + _r) * HD + (tid & 7) * 8);            \
            cp16(_ko + 9216 + _r * ROWB + (tid & 7) * 16,                       \
                 vg + ((size_t)(c) * 64 + _r) * HD + (tid & 7) * 8);            \
        }                                                                       \
        CP_COMMIT();                                                            \
    } while (0)

    KVLOAD(0, 0);
    KVLOAD(1, 1);

    // Q fragments (scaled by 1/8)
    CP_WAIT2();
    __syncthreads();
    uint32_t qf[4][4];
    {
        const uint32_t qaB = sb + QOFF + (wid * 16 + (lane & 15)) * ROWB + (lane >> 4) * 16;
#pragma unroll
        for (int ck = 0; ck < 4; ck++) {
            ldsm4(qf[ck], qaB + ck * 32);
#pragma unroll
            for (int i = 0; i < 4; i++) qf[ck][i] = hmul2(qf[ck][i], 0x30003000u); // x0.125
        }
    }

    float o[8][4];
#pragma unroll
    for (int nt = 0; nt < 8; nt++)
#pragma unroll
        for (int t = 0; t < 4; t++) o[nt][t] = 0.f;
    float m0r = -1e30f, m1r = -1e30f, l0 = 0.f, l1 = 0.f;

    for (int c = 0; c < nc; c++) {
        if (c < nc - 1) { CP_WAIT1(); } else { CP_WAIT0(); }
        __syncthreads();
        const uint32_t kof = sb + KOFF + (uint32_t)(c & 1) * KVST;
        const int k0 = c * 64;
        const bool active = (k0 <= q0 + wid * 16 + 15);

        if (active) {
            // S = Q K^T
            float s[8][4];
#pragma unroll
            for (int jt = 0; jt < 8; jt++)
#pragma unroll
                for (int t = 0; t < 4; t++) s[jt][t] = 0.f;

            const uint32_t kbB = kof + ((lane >> 4) * 8 + (lane & 7)) * ROWB
                               + ((lane >> 3) & 1) * 16;
#pragma unroll
            for (int ck = 0; ck < 4; ck++) {
                uint32_t b[8][2];
#pragma unroll
                for (int jp = 0; jp < 4; jp++) {
                    uint32_t r[4];
                    ldsm4(r, kbB + jp * 16 * ROWB + ck * 32);
                    b[2 * jp][0] = r[0]; b[2 * jp][1] = r[1];
                    b[2 * jp + 1][0] = r[2]; b[2 * jp + 1][1] = r[3];
                }
#pragma unroll
                for (int jt = 0; jt < 8; jt++) mma_f16(s[jt], qf[ck], b[jt]);
            }

            // causal mask (boundary chunks only)
            if (k0 + 63 > q0 + wid * 16) {
                const int r0w = q0 + wid * 16 + gid;
#pragma unroll
                for (int jt = 0; jt < 8; jt++) {
                    const int cl = k0 + jt * 8 + tig * 2;
                    if (cl > r0w)     s[jt][0] = -1e30f;
                    if (cl + 1 > r0w) s[jt][1] = -1e30f;
                    if (cl > r0w + 8)     s[jt][2] = -1e30f;
                    if (cl + 1 > r0w + 8) s[jt][3] = -1e30f;
                }
            }

            // online softmax
            float mx0 = -1e30f, mx1 = -1e30f;
#pragma unroll
            for (int jt = 0; jt < 8; jt++) {
                mx0 = fmaxf(mx0, fmaxf(s[jt][0], s[jt][1]));
                mx1 = fmaxf(mx1, fmaxf(s[jt][2], s[jt][3]));
            }
            mx0 = fmaxf(mx0, __shfl_xor_sync(0xFFFFFFFF, mx0, 1));
            mx0 = fmaxf(mx0, __shfl_xor_sync(0xFFFFFFFF, mx0, 2));
            mx1 = fmaxf(mx1, __shfl_xor_sync(0xFFFFFFFF, mx1, 1));
            mx1 = fmaxf(mx1, __shfl_xor_sync(0xFFFFFFFF, mx1, 2));
            const float mn0 = fmaxf(m0r, mx0), mn1 = fmaxf(m1r, mx1);
            const float a0 = __expf(m0r - mn0), a1 = __expf(m1r - mn1);
            float s0 = 0.f, s1 = 0.f;
#pragma unroll
            for (int jt = 0; jt < 8; jt++) {
                s[jt][0] = __expf(s[jt][0] - mn0); s0 += s[jt][0];
                s[jt][1] = __expf(s[jt][1] - mn0); s0 += s[jt][1];
                s[jt][2] = __expf(s[jt][2] - mn1); s1 += s[jt][2];
                s[jt][3] = __expf(s[jt][3] - mn1); s1 += s[jt][3];
            }
            s0 += __shfl_xor_sync(0xFFFFFFFF, s0, 1);
            s0 += __shfl_xor_sync(0xFFFFFFFF, s0, 2);
            s1 += __shfl_xor_sync(0xFFFFFFFF, s1, 1);
            s1 += __shfl_xor_sync(0xFFFFFFFF, s1, 2);
            l0 = l0 * a0 + s0; l1 = l1 * a1 + s1;
            m0r = mn0; m1r = mn1;
#pragma unroll
            for (int nt = 0; nt < 8; nt++) {
                o[nt][0] *= a0; o[nt][1] *= a0; o[nt][2] *= a1; o[nt][3] *= a1;
            }

            // P -> fp16 A-fragments (accumulator/A-operand layout identity)
            uint32_t pf[4][4];
#pragma unroll
            for (int ck = 0; ck < 4; ck++) {
                pf[ck][0] = packh2(s[2 * ck][0], s[2 * ck][1]);
                pf[ck][1] = packh2(s[2 * ck][2], s[2 * ck][3]);
                pf[ck][2] = packh2(s[2 * ck + 1][0], s[2 * ck + 1][1]);
                pf[ck][3] = packh2(s[2 * ck + 1][2], s[2 * ck + 1][3]);
            }

            // O += P V
            const uint32_t vbB = kof + 9216 + (((lane >> 3) & 1) * 8 + (lane & 7)) * ROWB
                               + (lane >> 4) * 16;
#pragma unroll
            for (int ck = 0; ck < 4; ck++) {
                uint32_t b[8][2];
#pragma unroll
                for (int np = 0; np < 4; np++) {
                    uint32_t r[4];
                    ldsm4t(r, vbB + ck * 16 * ROWB + np * 32);
                    b[2 * np][0] = r[0]; b[2 * np][1] = r[1];
                    b[2 * np + 1][0] = r[2]; b[2 * np + 1][1] = r[3];
                }
#pragma unroll
                for (int nt = 0; nt < 8; nt++) mma_f16(o[nt], pf[ck], b[nt]);
            }
        }

        __syncthreads();
        if (c + 2 < nc) KVLOAD(c + 2, c & 1);
    }
#undef KVLOAD

    // epilogue: write 2-segment fp16 split [hi|lo] rows of g_acat
    const float i0 = 1.f / l0, i1 = 1.f / l1;
    const int b = bh >> 4, h = bh & 15;
    const size_t mr0 = (size_t)b * TLEN + q0 + wid * 16 + gid;
#pragma unroll
    for (int nt = 0; nt < 8; nt++) {
        const int cl = h * 64 + nt * 8 + tig * 2;
        {
            const float v0 = o[nt][0] * i0, v1 = o[nt][1] * i0;
            const float h0 = __half2float(__float2half_rn(v0));
            const float h1 = __half2float(__float2half_rn(v1));
            const uint32_t hp = packh2(v0, v1), lp = packh2(v0 - h0, v1 - h1);
            __half* base = g_acat + mr0 * KCAT + cl;
            *(uint32_t*)(base) = hp;
            *(uint32_t*)(base + CDIM) = lp;
        }
        {
            const float v0 = o[nt][2] * i1, v1 = o[nt][3] * i1;
            const float h0 = __half2float(__float2half_rn(v0));
            const float h1 = __half2float(__float2half_rn(v1));
            const uint32_t hp = packh2(v0, v1), lp = packh2(v0 - h0, v1 - h1);
            __half* base = g_acat + (mr0 + 8) * KCAT + cl;
            *(uint32_t*)(base) = hp;
            *(uint32_t*)(base + CDIM) = lp;
        }
    }
}

// ---------------------------------------------------------------------------
extern "C" void kernel_launch(void* const* d_in, const int* in_sizes, int n_in,
                              void* d_out, int out_size)
{
    (void)in_sizes; (void)n_in; (void)out_size;
    const float* x  = (const float*)d_in[0];
    const float* Wq = (const float*)d_in[1];
    const float* bq = (const float*)d_in[2];
    const float* Wk = (const float*)d_in[3];
    const float* bk = (const float*)d_in[4];
    const float* Wv = (const float*)d_in[5];
    const float* bv = (const float*)d_in[6];
    const float* Wp = (const float*)d_in[7];
    const float* bp = (const float*)d_in[8];
    float* out = (float*)d_out;

    cudaFuncSetAttribute(mm_qkv, cudaFuncAttributeMaxDynamicSharedMemorySize, GSM);
    cudaFuncSetAttribute(mm_proj, cudaFuncAttributeMaxDynamicSharedMemorySize, GSM);
    cudaFuncSetAttribute(flash_mma, cudaFuncAttributeMaxDynamicSharedMemorySize, FSM);

    split_act<<<MROWS, 256>>>(x);
    split_wt<<<dim3(CDIM, 4), 256>>>(Wq, Wk, Wv, Wp);

    mm_qkv<<<dim3(CDIM / 128, MROWS / 128, 3), 256, GSM>>>(bq, bk, bv);
    flash_mma<<<dim3(TLEN / 128, BSZ * NH), 256, FSM>>>();
    mm_proj<<<dim3(CDIM / 128, MROWS / 128), 256, GSM>>>(bp, out);
}

// round 5
// speedup vs baseline: 5.0543x; 1.1176x over previous
#include <cuda_runtime.h>
#include <cuda_fp16.h>
#include <cstdint>

#define BSZ 4
#define TLEN 2048
#define CDIM 1024
#define NH 16
#define HD 64
#define MROWS 8192
#define KCAT 2048

// ---------------- scratch ----------------
__device__ __half g_q[(size_t)MROWS * CDIM];     // [b,h,t,d]
__device__ __half g_k[(size_t)MROWS * CDIM];
__device__ __half g_v[(size_t)MROWS * CDIM];
__device__ __half g_xcat[(size_t)MROWS * KCAT];        // acts  [hi|lo]
__device__ __half g_acat[(size_t)MROWS * CDIM];        // attn out (hi only)
__device__ __half g_wcat[(size_t)3 * CDIM * KCAT];     // qkv weights [hi|hi] x3
__device__ __half g_wp[(size_t)CDIM * CDIM];           // proj weight (hi only)

// ---------------- PTX helpers ----------------
__device__ __forceinline__ uint32_t cvta_sm(const void* p) {
    uint32_t a;
    asm("{ .reg .u64 t; cvta.to.shared.u64 t, %1; cvt.u32.u64 %0, t; }" : "=r"(a) : "l"(p));
    return a;
}
__device__ __forceinline__ void cp16(uint32_t s, const void* g) {
    asm volatile("cp.async.cg.shared.global [%0], [%1], 16;" :: "r"(s), "l"(g));
}
#define CP_COMMIT() asm volatile("cp.async.commit_group;" ::: "memory")
#define CP_WAIT0()  asm volatile("cp.async.wait_group 0;" ::: "memory")
#define CP_WAIT1()  asm volatile("cp.async.wait_group 1;" ::: "memory")
#define CP_WAIT2()  asm volatile("cp.async.wait_group 2;" ::: "memory")

__device__ __forceinline__ void ldsm4(uint32_t* r, uint32_t a) {
    asm volatile("ldmatrix.sync.aligned.m8n8.x4.shared.b16 {%0,%1,%2,%3}, [%4];"
                 : "=r"(r[0]), "=r"(r[1]), "=r"(r[2]), "=r"(r[3]) : "r"(a));
}
__device__ __forceinline__ void ldsm4t(uint32_t* r, uint32_t a) {
    asm volatile("ldmatrix.sync.aligned.m8n8.x4.trans.shared.b16 {%0,%1,%2,%3}, [%4];"
                 : "=r"(r[0]), "=r"(r[1]), "=r"(r[2]), "=r"(r[3]) : "r"(a));
}
__device__ __forceinline__ void mma_f16(float* c, const uint32_t* a, const uint32_t* b) {
    asm volatile(
        "mma.sync.aligned.m16n8k16.row.col.f32.f16.f16.f32 "
        "{%0,%1,%2,%3}, {%4,%5,%6,%7}, {%8,%9}, {%0,%1,%2,%3};"
        : "+f"(c[0]), "+f"(c[1]), "+f"(c[2]), "+f"(c[3])
        : "r"(a[0]), "r"(a[1]), "r"(a[2]), "r"(a[3]), "r"(b[0]), "r"(b[1]));
}
__device__ __forceinline__ uint32_t packh2(float lo, float hi) {  // f16x2 {lo, hi}
    uint32_t d;
    asm("cvt.rn.f16x2.f32 %0, %1, %2;" : "=r"(d) : "f"(hi), "f"(lo));
    return d;
}
__device__ __forceinline__ uint32_t hmul2(uint32_t a, uint32_t b) {
    uint32_t d;
    asm("mul.f16x2 %0, %1, %2;" : "=r"(d) : "r"(a), "r"(b));
    return d;
}

// ---------------------------------------------------------------------------
// Splits
// ---------------------------------------------------------------------------
__global__ void split_act(const float* __restrict__ in)
{
    const int r = blockIdx.x, q = threadIdx.x * 4;
    float4 v = *(const float4*)(in + (size_t)r * CDIM + q);
    float f[4] = {v.x, v.y, v.z, v.w}, lo[4];
#pragma unroll
    for (int j = 0; j < 4; j++)
        lo[j] = f[j] - __half2float(__float2half_rn(f[j]));
    uint2 hp = {packh2(f[0], f[1]), packh2(f[2], f[3])};
    uint2 lp = {packh2(lo[0], lo[1]), packh2(lo[2], lo[3])};
    __half* o = g_xcat + (size_t)r * KCAT + q;
    *(uint2*)(o) = hp; *(uint2*)(o + CDIM) = lp;
}
__global__ void split_wt(const float* __restrict__ W0, const float* __restrict__ W1,
                         const float* __restrict__ W2, const float* __restrict__ W3)
{
    const int z = blockIdx.y;
    const float* W = (z == 0) ? W0 : (z == 1) ? W1 : (z == 2) ? W2 : W3;
    const int r = blockIdx.x, q = threadIdx.x * 4;
    float4 v = *(const float4*)(W + (size_t)r * CDIM + q);
    uint2 hp = {packh2(v.x, v.y), packh2(v.z, v.w)};
    if (z < 3) {
        __half* o = g_wcat + (size_t)z * CDIM * KCAT + (size_t)r * KCAT + q;
        *(uint2*)(o) = hp; *(uint2*)(o + CDIM) = hp;
    } else {
        *(uint2*)(g_wp + (size_t)r * CDIM + q) = hp;
    }
}

// ---------------------------------------------------------------------------
// HMMA GEMM: D[m,n] = A[m,:] . W[n,:] + bias[n]
// CTA 128x128, 8 warps (2m x 4n), warp 64x32. k-chunk 64, 3-stage cp.async,
// single __syncthreads per mainloop iteration (CUTLASS multistage order).
// smem rows padded to 72 halves (144B) -> conflict-free ldmatrix.
// ---------------------------------------------------------------------------
#define ROWB 144
#define ATILE (128 * ROWB)      // 18432
#define STG   (2 * ATILE)       // 36864 per stage (A + W)
#define GSM   (3 * STG)         // 110592

template<int KA, int KW, int NCH>
__device__ __forceinline__ void gemm_mma(const __half* __restrict__ A,
                                         const __half* __restrict__ W,
                                         const float* __restrict__ bias,
                                         __half* dsth, float* dstf, int head)
{
    extern __shared__ char sm_g[];
    const uint32_t sb = cvta_sm(sm_g);
    const int tid = threadIdx.x, lane = tid & 31, wid = tid >> 5;
    const int m0 = blockIdx.y * 128, n0 = blockIdx.x * 128;
    const int wm = wid & 1, wn = wid >> 1;
    const int gid = lane >> 2, tig = lane & 3;

    const int lr = tid >> 3, lc = tid & 7;
    const __half* gA = A + (size_t)(m0 + lr) * KA + lc * 8;
    const __half* gW = W + (size_t)(n0 + lr) * KW + lc * 8;
    const uint32_t sA0 = sb + lr * ROWB + lc * 16;
    const uint32_t sW0 = sA0 + ATILE;

#define GLOAD(ch, st) do {                                                      \
        const uint32_t _o = (uint32_t)(st) * STG;                               \
        _Pragma("unroll")                                                       \
        for (int _i = 0; _i < 4; _i++) {                                        \
            cp16(sA0 + _o + _i * 32 * ROWB, gA + (size_t)_i * 32 * KA + (ch) * 64); \
            cp16(sW0 + _o + _i * 32 * ROWB, gW + (size_t)_i * 32 * KW + (ch) * 64); \
        }                                                                       \
        CP_COMMIT();                                                            \
    } while (0)

    float acc[4][4][4];
#pragma unroll
    for (int i = 0; i < 4; i++)
#pragma unroll
        for (int j = 0; j < 4; j++)
#pragma unroll
            for (int t = 0; t < 4; t++) acc[i][j][t] = 0.f;

    const uint32_t aB = sb + (wm * 64 + (lane & 15)) * ROWB + (lane >> 4) * 16;
    const uint32_t bB = sb + ATILE + (wn * 32 + (lane >> 4) * 8 + (lane & 7)) * ROWB
                      + ((lane >> 3) & 1) * 16;

    GLOAD(0, 0);
    GLOAD(1, 1);

    for (int k = 0; k < NCH; k++) {
        if (k < NCH - 1) { CP_WAIT1(); } else { CP_WAIT0(); }
        __syncthreads();
        if (k + 2 < NCH) GLOAD(k + 2, (k + 2) % 3);   // stage freed at iter k-1
        const uint32_t so = (uint32_t)(k % 3) * STG;
#pragma unroll
        for (int ck = 0; ck < 4; ck++) {
            uint32_t a[4][4], b[4][2];
#pragma unroll
            for (int mt = 0; mt < 4; mt++)
                ldsm4(a[mt], aB + so + mt * 16 * ROWB + ck * 32);
#pragma unroll
            for (int np = 0; np < 2; np++) {
                uint32_t r[4];
                ldsm4(r, bB + so + np * 16 * ROWB + ck * 32);
                b[2 * np][0] = r[0]; b[2 * np][1] = r[1];
                b[2 * np + 1][0] = r[2]; b[2 * np + 1][1] = r[3];
            }
#pragma unroll
            for (int mt = 0; mt < 4; mt++)
#pragma unroll
                for (int nt = 0; nt < 4; nt++)
                    mma_f16(acc[mt][nt], a[mt], b[nt]);
        }
    }
#undef GLOAD

    // epilogue
#pragma unroll
    for (int mt = 0; mt < 4; mt++) {
        const int mr0 = m0 + wm * 64 + mt * 16 + gid;
#pragma unroll
        for (int nt = 0; nt < 4; nt++) {
            const int n = n0 + wn * 32 + nt * 8 + tig * 2;
            const float b0 = bias[n], b1 = bias[n + 1];
            const float v00 = acc[mt][nt][0] + b0, v01 = acc[mt][nt][1] + b1;
            const float v10 = acc[mt][nt][2] + b0, v11 = acc[mt][nt][3] + b1;
            if (head) {
                const int h = n >> 6, d = n & 63;
                {
                    const int m = mr0, bb = m >> 11, t = m & 2047;
                    *(uint32_t*)(dsth + (((size_t)(bb * NH + h)) * TLEN + t) * HD + d)
                        = packh2(v00, v01);
                }
                {
                    const int m = mr0 + 8, bb = m >> 11, t = m & 2047;
                    *(uint32_t*)(dsth + (((size_t)(bb * NH + h)) * TLEN + t) * HD + d)
                        = packh2(v10, v11);
                }
            } else {
                float2 p0 = {v00, v01}, p1 = {v10, v11};
                *(float2*)(dstf + (size_t)mr0 * CDIM + n) = p0;
                *(float2*)(dstf + (size_t)(mr0 + 8) * CDIM + n) = p1;
            }
        }
    }
}

__global__ __launch_bounds__(256, 2)
void mm_qkv(const float* __restrict__ bq, const float* __restrict__ bk,
            const float* __restrict__ bv)
{
    const int z = blockIdx.z;
    const __half* W = g_wcat + (size_t)z * CDIM * KCAT;
    const float* bias = (z == 0) ? bq : (z == 1) ? bk : bv;
    __half* dst = (z == 0) ? g_q : (z == 1) ? g_k : g_v;
    gemm_mma<KCAT, KCAT, 32>(g_xcat, W, bias, dst, nullptr, 1);
}
__global__ __launch_bounds__(256, 2)
void mm_proj(const float* __restrict__ bp, float* __restrict__ out)
{
    gemm_mma<CDIM, CDIM, 16>(g_acat, g_wp, bp, nullptr, out, 0);
}

// ---------------------------------------------------------------------------
// Flash attention, HMMA fp16. CTA = 128 q rows x one (b,h); 8 warps x 16 rows.
// K/V chunks of 64, 3-stage cp.async, single sync per chunk.
// Epilogue writes fp16 (hi) into g_acat.
// ---------------------------------------------------------------------------
#define QOFF 0
#define KOFF 18432
#define KVST 18432
#define FSM  (KOFF + 3 * KVST)   // 73728

__global__ __launch_bounds__(256, 2)
void flash_mma()
{
    extern __shared__ char sm_f[];
    const uint32_t sb = cvta_sm(sm_f);
    const int tid = threadIdx.x, lane = tid & 31, wid = tid >> 5;
    const int gid = lane >> 2, tig = lane & 3;
    const int bh = blockIdx.y;
    const int qb = 15 - blockIdx.x;          // big tiles first (LPT)
    const int q0 = qb * 128;
    const int nc = 2 * (qb + 1);

    const __half* qg = g_q + (size_t)bh * TLEN * HD;
    const __half* kg = g_k + (size_t)bh * TLEN * HD;
    const __half* vg = g_v + (size_t)bh * TLEN * HD;

    // Q load (group 0)
#pragma unroll
    for (int i = 0; i < 4; i++) {
        const int r = (tid >> 3) + 32 * i;
        cp16(sb + QOFF + r * ROWB + (tid & 7) * 16,
             qg + ((size_t)(q0 + r)) * HD + (tid & 7) * 8);
    }
    CP_COMMIT();

#define KVLOAD(c, st) do {                                                      \
        const uint32_t _ko = sb + KOFF + (uint32_t)(st) * KVST;                 \
        _Pragma("unroll")                                                       \
        for (int _i = 0; _i < 2; _i++) {                                        \
            const int _r = (tid >> 3) + 32 * _i;                                \
            cp16(_ko + _r * ROWB + (tid & 7) * 16,                              \
                 kg + ((size_t)(c) * 64 + _r) * HD + (tid & 7) * 8);            \
            cp16(_ko + 9216 + _r * ROWB + (tid & 7) * 16,                       \
                 vg + ((size_t)(c) * 64 + _r) * HD + (tid & 7) * 8);            \
        }                                                                       \
        CP_COMMIT();                                                            \
    } while (0)

    KVLOAD(0, 0);
    KVLOAD(1, 1);

    // Q fragments (scaled by 1/8)
    CP_WAIT2();
    __syncthreads();
    uint32_t qf[4][4];
    {
        const uint32_t qaB = sb + QOFF + (wid * 16 + (lane & 15)) * ROWB + (lane >> 4) * 16;
#pragma unroll
        for (int ck = 0; ck < 4; ck++) {
            ldsm4(qf[ck], qaB + ck * 32);
#pragma unroll
            for (int i = 0; i < 4; i++) qf[ck][i] = hmul2(qf[ck][i], 0x30003000u); // x0.125
        }
    }

    float o[8][4];
#pragma unroll
    for (int nt = 0; nt < 8; nt++)
#pragma unroll
        for (int t = 0; t < 4; t++) o[nt][t] = 0.f;
    float m0r = -1e30f, m1r = -1e30f, l0 = 0.f, l1 = 0.f;

    for (int c = 0; c < nc; c++) {
        if (c < nc - 1) { CP_WAIT1(); } else { CP_WAIT0(); }
        __syncthreads();
        if (c + 2 < nc) KVLOAD(c + 2, (c + 2) % 3);   // stage freed at iter c-1
        const uint32_t kof = sb + KOFF + (uint32_t)(c % 3) * KVST;
        const int k0 = c * 64;
        const bool active = (k0 <= q0 + wid * 16 + 15);

        if (active) {
            // S = Q K^T
            float s[8][4];
#pragma unroll
            for (int jt = 0; jt < 8; jt++)
#pragma unroll
                for (int t = 0; t < 4; t++) s[jt][t] = 0.f;

            const uint32_t kbB = kof + ((lane >> 4) * 8 + (lane & 7)) * ROWB
                               + ((lane >> 3) & 1) * 16;
#pragma unroll
            for (int ck = 0; ck < 4; ck++) {
                uint32_t b[8][2];
#pragma unroll
                for (int jp = 0; jp < 4; jp++) {
                    uint32_t r[4];
                    ldsm4(r, kbB + jp * 16 * ROWB + ck * 32);
                    b[2 * jp][0] = r[0]; b[2 * jp][1] = r[1];
                    b[2 * jp + 1][0] = r[2]; b[2 * jp + 1][1] = r[3];
                }
#pragma unroll
                for (int jt = 0; jt < 8; jt++) mma_f16(s[jt], qf[ck], b[jt]);
            }

            // causal mask (boundary chunks only)
            if (k0 + 63 > q0 + wid * 16) {
                const int r0w = q0 + wid * 16 + gid;
#pragma unroll
                for (int jt = 0; jt < 8; jt++) {
                    const int cl = k0 + jt * 8 + tig * 2;
                    if (cl > r0w)     s[jt][0] = -1e30f;
                    if (cl + 1 > r0w) s[jt][1] = -1e30f;
                    if (cl > r0w + 8)     s[jt][2] = -1e30f;
                    if (cl + 1 > r0w + 8) s[jt][3] = -1e30f;
                }
            }

            // online softmax
            float mx0 = -1e30f, mx1 = -1e30f;
#pragma unroll
            for (int jt = 0; jt < 8; jt++) {
                mx0 = fmaxf(mx0, fmaxf(s[jt][0], s[jt][1]));
                mx1 = fmaxf(mx1, fmaxf(s[jt][2], s[jt][3]));
            }
            mx0 = fmaxf(mx0, __shfl_xor_sync(0xFFFFFFFF, mx0, 1));
            mx0 = fmaxf(mx0, __shfl_xor_sync(0xFFFFFFFF, mx0, 2));
            mx1 = fmaxf(mx1, __shfl_xor_sync(0xFFFFFFFF, mx1, 1));
            mx1 = fmaxf(mx1, __shfl_xor_sync(0xFFFFFFFF, mx1, 2));
            const float mn0 = fmaxf(m0r, mx0), mn1 = fmaxf(m1r, mx1);
            const float a0 = __expf(m0r - mn0), a1 = __expf(m1r - mn1);
            float s0 = 0.f, s1 = 0.f;
#pragma unroll
            for (int jt = 0; jt < 8; jt++) {
                s[jt][0] = __expf(s[jt][0] - mn0); s0 += s[jt][0];
                s[jt][1] = __expf(s[jt][1] - mn0); s0 += s[jt][1];
                s[jt][2] = __expf(s[jt][2] - mn1); s1 += s[jt][2];
                s[jt][3] = __expf(s[jt][3] - mn1); s1 += s[jt][3];
            }
            s0 += __shfl_xor_sync(0xFFFFFFFF, s0, 1);
            s0 += __shfl_xor_sync(0xFFFFFFFF, s0, 2);
            s1 += __shfl_xor_sync(0xFFFFFFFF, s1, 1);
            s1 += __shfl_xor_sync(0xFFFFFFFF, s1, 2);
            l0 = l0 * a0 + s0; l1 = l1 * a1 + s1;
            m0r = mn0; m1r = mn1;
#pragma unroll
            for (int nt = 0; nt < 8; nt++) {
                o[nt][0] *= a0; o[nt][1] *= a0; o[nt][2] *= a1; o[nt][3] *= a1;
            }

            // P -> fp16 A-fragments (accumulator/A-operand layout identity)
            uint32_t pf[4][4];
#pragma unroll
            for (int ck = 0; ck < 4; ck++) {
                pf[ck][0] = packh2(s[2 * ck][0], s[2 * ck][1]);
                pf[ck][1] = packh2(s[2 * ck][2], s[2 * ck][3]);
                pf[ck][2] = packh2(s[2 * ck + 1][0], s[2 * ck + 1][1]);
                pf[ck][3] = packh2(s[2 * ck + 1][2], s[2 * ck + 1][3]);
            }

            // O += P V
            const uint32_t vbB = kof + 9216 + (((lane >> 3) & 1) * 8 + (lane & 7)) * ROWB
                               + (lane >> 4) * 16;
#pragma unroll
            for (int ck = 0; ck < 4; ck++) {
                uint32_t b[8][2];
#pragma unroll
                for (int np = 0; np < 4; np++) {
                    uint32_t r[4];
                    ldsm4t(r, vbB + ck * 16 * ROWB + np * 32);
                    b[2 * np][0] = r[0]; b[2 * np][1] = r[1];
                    b[2 * np + 1][0] = r[2]; b[2 * np + 1][1] = r[3];
                }
#pragma unroll
                for (int nt = 0; nt < 8; nt++) mma_f16(o[nt], pf[ck], b[nt]);
            }
        }
    }
#undef KVLOAD

    // epilogue: write fp16 rows of g_acat (hi only)
    const float i0 = 1.f / l0, i1 = 1.f / l1;
    const int b = bh >> 4, h = bh & 15;
    const size_t mr0 = (size_t)b * TLEN + q0 + wid * 16 + gid;
#pragma unroll
    for (int nt = 0; nt < 8; nt++) {
        const int cl = h * 64 + nt * 8 + tig * 2;
        *(uint32_t*)(g_acat + mr0 * CDIM + cl) =
            packh2(o[nt][0] * i0, o[nt][1] * i0);
        *(uint32_t*)(g_acat + (mr0 + 8) * CDIM + cl) =
            packh2(o[nt][2] * i1, o[nt][3] * i1);
    }
}

// ---------------------------------------------------------------------------
extern "C" void kernel_launch(void* const* d_in, const int* in_sizes, int n_in,
                              void* d_out, int out_size)
{
    (void)in_sizes; (void)n_in; (void)out_size;
    const float* x  = (const float*)d_in[0];
    const float* Wq = (const float*)d_in[1];
    const float* bq = (const float*)d_in[2];
    const float* Wk = (const float*)d_in[3];
    const float* bk = (const float*)d_in[4];
    const float* Wv = (const float*)d_in[5];
    const float* bv = (const float*)d_in[6];
    const float* Wp = (const float*)d_in[7];
    const float* bp = (const float*)d_in[8];
    float* out = (float*)d_out;

    cudaFuncSetAttribute(mm_qkv, cudaFuncAttributeMaxDynamicSharedMemorySize, GSM);
    cudaFuncSetAttribute(mm_proj, cudaFuncAttributeMaxDynamicSharedMemorySize, GSM);
    cudaFuncSetAttribute(flash_mma, cudaFuncAttributeMaxDynamicSharedMemorySize, FSM);

    split_act<<<MROWS, 256>>>(x);
    split_wt<<<dim3(CDIM, 4), 256>>>(Wq, Wk, Wv, Wp);

    mm_qkv<<<dim3(CDIM / 128, MROWS / 128, 3), 256, GSM>>>(bq, bk, bv);
    flash_mma<<<dim3(TLEN / 128, BSZ * NH), 256, FSM>>>();
    mm_proj<<<dim3(CDIM / 128, MROWS / 128), 256, GSM>>>(bp, out);
}